// round 4
// baseline (speedup 1.0000x reference)
#include <cuda_runtime.h>
#include <cuda_bf16.h>
#include <math.h>
#include <stdint.h>

// Problem constants
constexpr int CB  = 2;
constexpr int CS  = 2048;
constexpr int CD  = 1024;
constexpr int CH  = 16;
constexpr int CHD = 64;

// Scratch (allocation-free rule: static __device__ arrays)
__device__ __align__(256) float g_q[CB * CS * CD];
__device__ __align__(256) float g_k[CB * CS * CD];
__device__ __align__(256) float g_v[CB * CS * CD];
__device__ __align__(256) float g_vals[CB * CS * CD];

// ---------------------------------------------------------------------------
// TF32 helpers
// ---------------------------------------------------------------------------
__device__ __forceinline__ uint32_t f2tf32(float x) {
    uint32_t u;
    asm("cvt.rna.tf32.f32 %0, %1;" : "=r"(u) : "f"(x));
    return u;
}

__device__ __forceinline__ void mma_tf32(float c[4], const uint32_t a[4],
                                         const uint32_t b[2]) {
    asm volatile(
        "mma.sync.aligned.m16n8k8.row.col.f32.tf32.tf32.f32 "
        "{%0,%1,%2,%3}, {%4,%5,%6,%7}, {%8,%9}, {%0,%1,%2,%3};"
        : "+f"(c[0]), "+f"(c[1]), "+f"(c[2]), "+f"(c[3])
        : "r"(a[0]), "r"(a[1]), "r"(a[2]), "r"(a[3]), "r"(b[0]), "r"(b[1]));
}

// ---------------------------------------------------------------------------
// TF32 tensor-core GEMM, 2-stage double-buffered, batched over blockIdx.z.
// C[M,N] = A[M,K] * W[K,N]. Block tile 128x128, BK=16, 256 threads.
// ---------------------------------------------------------------------------
constexpr int BM = 128, BN = 128, BKt = 16;

__global__ __launch_bounds__(256) void sgemm_tf32_v2(
    const float* __restrict__ A0, const float* __restrict__ A1,
    const float* __restrict__ A2, const float* __restrict__ W0,
    const float* __restrict__ W1, const float* __restrict__ W2,
    float* __restrict__ C0, float* __restrict__ C1, float* __restrict__ C2,
    int M, int N, int K) {
    __shared__ uint32_t As[2][BKt][BM + 4];
    __shared__ uint32_t Bs[2][BKt][BN + 4];

    const int z = blockIdx.z;
    const float* A = (z == 0) ? A0 : (z == 1) ? A1 : A2;
    const float* W = (z == 0) ? W0 : (z == 1) ? W1 : W2;
    float*       C = (z == 0) ? C0 : (z == 1) ? C1 : C2;

    const int t    = threadIdx.x;
    const int lane = t & 31;
    const int warp = t >> 5;
    const int wm   = warp & 1;   // 0..1
    const int wn   = warp >> 1;  // 0..3
    const int gid  = lane >> 2;  // 0..7
    const int tg   = lane & 3;   // 0..3

    const int m0b = blockIdx.y * BM;
    const int n0b = blockIdx.x * BN;

    const int arow = t >> 2;        // 0..63
    const int acol = (t & 3) * 4;   // 0..12
    const int brow = t >> 4;        // 0..15
    const int bcol = (t & 15) * 4;  // 0..60

    float4 aRegs[2], bRegs[2];

    float c[4][4][4];
#pragma unroll
    for (int mt = 0; mt < 4; ++mt)
#pragma unroll
        for (int nt = 0; nt < 4; ++nt)
#pragma unroll
            for (int i = 0; i < 4; ++i) c[mt][nt][i] = 0.f;

    // prologue: fill stage 0 with tile 0
    {
        aRegs[0] = *(const float4*)&A[(size_t)(m0b + arow) * K + acol];
        aRegs[1] = *(const float4*)&A[(size_t)(m0b + arow + 64) * K + acol];
        bRegs[0] = *(const float4*)&W[(size_t)brow * N + n0b + bcol];
        bRegs[1] = *(const float4*)&W[(size_t)brow * N + n0b + bcol + 64];
#pragma unroll
        for (int i = 0; i < 2; ++i) {
            const float* f = (const float*)&aRegs[i];
#pragma unroll
            for (int j = 0; j < 4; ++j) As[0][acol + j][arow + i * 64] = f2tf32(f[j]);
        }
#pragma unroll
        for (int i = 0; i < 2; ++i) {
            const float* f = (const float*)&bRegs[i];
#pragma unroll
            for (int j = 0; j < 4; ++j) Bs[0][brow][bcol + i * 64 + j] = f2tf32(f[j]);
        }
    }
    __syncthreads();

    int stage = 0;
    for (int k0 = 0; k0 < K; k0 += BKt) {
        const bool has_next = (k0 + BKt < K);
        if (has_next) {
            const int kn = k0 + BKt;
            aRegs[0] = *(const float4*)&A[(size_t)(m0b + arow) * K + kn + acol];
            aRegs[1] = *(const float4*)&A[(size_t)(m0b + arow + 64) * K + kn + acol];
            bRegs[0] = *(const float4*)&W[(size_t)(kn + brow) * N + n0b + bcol];
            bRegs[1] = *(const float4*)&W[(size_t)(kn + brow) * N + n0b + bcol + 64];
        }

#pragma unroll
        for (int kk = 0; kk < BKt; kk += 8) {
            uint32_t af[4][4], bf[4][2];
#pragma unroll
            for (int mt = 0; mt < 4; ++mt) {
                const int mm = wm * 64 + mt * 16 + gid;
                af[mt][0] = As[stage][kk + tg][mm];
                af[mt][1] = As[stage][kk + tg][mm + 8];
                af[mt][2] = As[stage][kk + tg + 4][mm];
                af[mt][3] = As[stage][kk + tg + 4][mm + 8];
            }
#pragma unroll
            for (int nt = 0; nt < 4; ++nt) {
                const int nn = wn * 32 + nt * 8 + gid;
                bf[nt][0] = Bs[stage][kk + tg][nn];
                bf[nt][1] = Bs[stage][kk + tg + 4][nn];
            }
#pragma unroll
            for (int mt = 0; mt < 4; ++mt)
#pragma unroll
                for (int nt = 0; nt < 4; ++nt) mma_tf32(c[mt][nt], af[mt], bf[nt]);
        }

        if (has_next) {
            const int ns = stage ^ 1;
#pragma unroll
            for (int i = 0; i < 2; ++i) {
                const float* f = (const float*)&aRegs[i];
#pragma unroll
                for (int j = 0; j < 4; ++j) As[ns][acol + j][arow + i * 64] = f2tf32(f[j]);
            }
#pragma unroll
            for (int i = 0; i < 2; ++i) {
                const float* f = (const float*)&bRegs[i];
#pragma unroll
                for (int j = 0; j < 4; ++j) Bs[ns][brow][bcol + i * 64 + j] = f2tf32(f[j]);
            }
            __syncthreads();
            stage = ns;
        }
    }

    // epilogue
#pragma unroll
    for (int mt = 0; mt < 4; ++mt) {
        const int r0 = m0b + wm * 64 + mt * 16 + gid;
#pragma unroll
        for (int nt = 0; nt < 4; ++nt) {
            const int cc = n0b + wn * 32 + nt * 8 + tg * 2;
            *(float2*)&C[(size_t)r0 * N + cc]       = make_float2(c[mt][nt][0], c[mt][nt][1]);
            *(float2*)&C[(size_t)(r0 + 8) * N + cc] = make_float2(c[mt][nt][2], c[mt][nt][3]);
        }
    }
}

// ---------------------------------------------------------------------------
// RoPE (bf16 cos/sin tables, matching reference) + RMSNorm, in place.
// ---------------------------------------------------------------------------
__global__ __launch_bounds__(256) void rope_rms_kernel(float* __restrict__ x) {
    const int gt   = blockIdx.x * blockDim.x + threadIdx.x;
    const int gw   = gt >> 5;
    const int lane = gt & 31;
    if (gw >= CB * CS * CH) return;

    const int sPos = (gw / CH) % CS;
    float* p = x + (size_t)gw * CHD;

    const float x1 = p[lane];
    const float x2 = p[lane + 32];

    const float ex = (float)(2 * lane) * (1.0f / 64.0f);
    const float fr = powf(100000.0f, ex);
    const float g  = (float)sPos * (1.0f / fr);
    const float cc = __bfloat162float(__float2bfloat16(cosf(g)));
    const float sn = __bfloat162float(__float2bfloat16(sinf(g)));

    const float y1 = x1 * cc + x2 * sn;
    const float y2 = -x1 * sn + x2 * cc;

    float ss = y1 * y1 + y2 * y2;
#pragma unroll
    for (int o = 16; o > 0; o >>= 1) ss += __shfl_xor_sync(0xffffffffu, ss, o);

    const float rms = sqrtf(ss * (1.0f / 64.0f) + 1e-9f);
    const float ir  = 1.0f / rms;
    p[lane]      = y1 * ir;
    p[lane + 32] = y2 * ir;
}

// ---------------------------------------------------------------------------
// Causal flash attention with TF32 tensor cores.
// Block: 128 q-rows for one (b,h); 256 threads = 8 warps (16 q-rows each).
// KV tiles of 32. Q a-fragments loaded directly from gmem (no Q smem).
// ---------------------------------------------------------------------------
__global__ __launch_bounds__(256) void flash_attn_tc(
    const float* __restrict__ q, const float* __restrict__ k,
    const float* __restrict__ v, float* __restrict__ o) {
    __shared__ uint32_t Ks[32][68];
    __shared__ uint32_t Vs[32][68];
    __shared__ uint32_t Ps[128][36];

    const int t    = threadIdx.x;
    const int lane = t & 31;
    const int warp = t >> 5;
    const int gid  = lane >> 2;  // 0..7
    const int tg   = lane & 3;   // 0..3

    const int q0 = blockIdx.x * 128;
    const int bh = blockIdx.y;
    const size_t base = ((size_t)(bh >> 4) * CS * CH + (bh & 15)) * CHD;
    const int rs = CH * CHD;  // 1024

    const int prow0 = warp * 16 + gid;      // local row in Ps
    const int prow1 = prow0 + 8;
    const int qrow0 = q0 + prow0;           // global q row
    const int qrow1 = qrow0 + 8;

    // Preload Q a-fragments directly from gmem (persist across all KV tiles)
    uint32_t qa[8][4];
#pragma unroll
    for (int ks = 0; ks < 8; ++ks) {
        qa[ks][0] = f2tf32(q[base + (size_t)qrow0 * rs + ks * 8 + tg]);
        qa[ks][1] = f2tf32(q[base + (size_t)qrow1 * rs + ks * 8 + tg]);
        qa[ks][2] = f2tf32(q[base + (size_t)qrow0 * rs + ks * 8 + tg + 4]);
        qa[ks][3] = f2tf32(q[base + (size_t)qrow1 * rs + ks * 8 + tg + 4]);
    }

    float oa[8][4];
#pragma unroll
    for (int dt = 0; dt < 8; ++dt)
#pragma unroll
        for (int i = 0; i < 4; ++i) oa[dt][i] = 0.f;

    float m0 = -1e30f, m1 = -1e30f, l0 = 0.f, l1 = 0.f;

    const int nkt = (q0 >> 5) + 4;
    for (int kt = 0; kt < nkt; ++kt) {
        const int kv0 = kt << 5;
        __syncthreads();  // previous tile's Ks/Vs reads done
        for (int i = t; i < 32 * 64; i += 256) {
            int rr = i >> 6, d = i & 63;
            size_t gi = base + (size_t)(kv0 + rr) * rs + d;
            Ks[rr][d] = f2tf32(k[gi]);
            Vs[rr][d] = f2tf32(v[gi]);
        }
        __syncthreads();

        // ---- scores: S = Q K^T (16x32 per warp) ----
        float sc[4][4];
#pragma unroll
        for (int nt = 0; nt < 4; ++nt)
#pragma unroll
            for (int i = 0; i < 4; ++i) sc[nt][i] = 0.f;

#pragma unroll
        for (int ks = 0; ks < 8; ++ks) {
#pragma unroll
            for (int nt = 0; nt < 4; ++nt) {
                uint32_t b[2];
                b[0] = Ks[nt * 8 + gid][ks * 8 + tg];
                b[1] = Ks[nt * 8 + gid][ks * 8 + tg + 4];
                mma_tf32(sc[nt], qa[ks], b);
            }
        }

        // ---- scale + causal mask ----
        const bool needmask = (kv0 + 31 > qrow0);
#pragma unroll
        for (int nt = 0; nt < 4; ++nt) {
            const int c0 = kv0 + nt * 8 + 2 * tg;
            const int c1 = c0 + 1;
            sc[nt][0] *= 0.125f;
            sc[nt][1] *= 0.125f;
            sc[nt][2] *= 0.125f;
            sc[nt][3] *= 0.125f;
            if (needmask) {
                if (c0 > qrow0) sc[nt][0] = -1e9f;
                if (c1 > qrow0) sc[nt][1] = -1e9f;
                if (c0 > qrow1) sc[nt][2] = -1e9f;
                if (c1 > qrow1) sc[nt][3] = -1e9f;
            }
        }

        // ---- online softmax (2 rows per thread, quad reductions) ----
        float tm0 = -1e30f, tm1 = -1e30f;
#pragma unroll
        for (int nt = 0; nt < 4; ++nt) {
            tm0 = fmaxf(tm0, fmaxf(sc[nt][0], sc[nt][1]));
            tm1 = fmaxf(tm1, fmaxf(sc[nt][2], sc[nt][3]));
        }
        tm0 = fmaxf(tm0, __shfl_xor_sync(0xffffffffu, tm0, 1));
        tm0 = fmaxf(tm0, __shfl_xor_sync(0xffffffffu, tm0, 2));
        tm1 = fmaxf(tm1, __shfl_xor_sync(0xffffffffu, tm1, 1));
        tm1 = fmaxf(tm1, __shfl_xor_sync(0xffffffffu, tm1, 2));

        const float m0n = fmaxf(m0, tm0);
        const float m1n = fmaxf(m1, tm1);
        const float a0  = __expf(m0 - m0n);
        const float a1  = __expf(m1 - m1n);

        float s0 = 0.f, s1 = 0.f;
#pragma unroll
        for (int nt = 0; nt < 4; ++nt) {
            const float p00 = __expf(sc[nt][0] - m0n);
            const float p01 = __expf(sc[nt][1] - m0n);
            const float p10 = __expf(sc[nt][2] - m1n);
            const float p11 = __expf(sc[nt][3] - m1n);
            s0 += p00 + p01;
            s1 += p10 + p11;
            const int cc = nt * 8 + 2 * tg;
            Ps[prow0][cc]     = f2tf32(p00);
            Ps[prow0][cc + 1] = f2tf32(p01);
            Ps[prow1][cc]     = f2tf32(p10);
            Ps[prow1][cc + 1] = f2tf32(p11);
        }
        s0 += __shfl_xor_sync(0xffffffffu, s0, 1);
        s0 += __shfl_xor_sync(0xffffffffu, s0, 2);
        s1 += __shfl_xor_sync(0xffffffffu, s1, 1);
        s1 += __shfl_xor_sync(0xffffffffu, s1, 2);

        l0 = l0 * a0 + s0;
        l1 = l1 * a1 + s1;
        m0 = m0n;
        m1 = m1n;

#pragma unroll
        for (int dt = 0; dt < 8; ++dt) {
            oa[dt][0] *= a0;
            oa[dt][1] *= a0;
            oa[dt][2] *= a1;
            oa[dt][3] *= a1;
        }
        __syncwarp();  // Ps rows are warp-private

        // ---- PV: O += P V (16x32 @ 32x64 per warp) ----
#pragma unroll
        for (int ks = 0; ks < 4; ++ks) {
            uint32_t pa[4];
            pa[0] = Ps[prow0][ks * 8 + tg];
            pa[1] = Ps[prow1][ks * 8 + tg];
            pa[2] = Ps[prow0][ks * 8 + tg + 4];
            pa[3] = Ps[prow1][ks * 8 + tg + 4];
#pragma unroll
            for (int dt = 0; dt < 8; ++dt) {
                uint32_t b[2];
                b[0] = Vs[ks * 8 + tg][dt * 8 + gid];
                b[1] = Vs[ks * 8 + tg + 4][dt * 8 + gid];
                mma_tf32(oa[dt], pa, b);
            }
        }
    }

    // ---- epilogue ----
    const float il0 = 1.0f / l0;
    const float il1 = 1.0f / l1;
#pragma unroll
    for (int dt = 0; dt < 8; ++dt) {
        const int cc = dt * 8 + 2 * tg;
        *(float2*)&o[base + (size_t)qrow0 * rs + cc] =
            make_float2(oa[dt][0] * il0, oa[dt][1] * il0);
        *(float2*)&o[base + (size_t)qrow1 * rs + cc] =
            make_float2(oa[dt][2] * il1, oa[dt][3] * il1);
    }
}

// ---------------------------------------------------------------------------
// Launch
// ---------------------------------------------------------------------------
extern "C" void kernel_launch(void* const* d_in, const int* in_sizes, int n_in,
                              void* d_out, int out_size) {
    (void)in_sizes; (void)n_in; (void)out_size;
    const float* Q  = (const float*)d_in[0];
    const float* K  = (const float*)d_in[1];
    const float* V  = (const float*)d_in[2];
    const float* Wq = (const float*)d_in[4];
    const float* Wk = (const float*)d_in[5];
    const float* Wv = (const float*)d_in[6];
    const float* Wo = (const float*)d_in[7];
    float* out = (float*)d_out;

    float *gq, *gk, *gv, *gvals;
    cudaGetSymbolAddress((void**)&gq, g_q);
    cudaGetSymbolAddress((void**)&gk, g_k);
    cudaGetSymbolAddress((void**)&gv, g_v);
    cudaGetSymbolAddress((void**)&gvals, g_vals);

    const int M = CB * CS;               // 4096

    // Batched QKV projections
    dim3 ggrid3(CD / BN, M / BM, 3);     // (8, 32, 3)
    sgemm_tf32_v2<<<ggrid3, 256>>>(Q, K, V, Wq, Wk, Wv, gq, gk, gv, M, CD, CD);

    const int nwarps = CB * CS * CH;     // 65536
    dim3 rgrid(nwarps / 8);
    rope_rms_kernel<<<rgrid, 256>>>(gq);
    rope_rms_kernel<<<rgrid, 256>>>(gk);

    dim3 agrid(CS / 128, CB * CH);       // (16, 32)
    flash_attn_tc<<<agrid, 256>>>(gq, gk, gv, gvals);

    // Output projection
    dim3 ggrid1(CD / BN, M / BM, 1);
    sgemm_tf32_v2<<<ggrid1, 256>>>(gvals, nullptr, nullptr, Wo, nullptr, nullptr,
                                   out, nullptr, nullptr, M, CD, CD);
}

// round 5
// speedup vs baseline: 1.0764x; 1.0764x over previous
#include <cuda_runtime.h>
#include <cuda_bf16.h>
#include <math.h>
#include <stdint.h>

// Problem constants
constexpr int CB  = 2;
constexpr int CS  = 2048;
constexpr int CD  = 1024;
constexpr int CH  = 16;
constexpr int CHD = 64;

// Scratch (allocation-free rule: static __device__ arrays)
__device__ __align__(256) float g_q[CB * CS * CD];
__device__ __align__(256) float g_k[CB * CS * CD];
__device__ __align__(256) float g_v[CB * CS * CD];
__device__ __align__(256) float g_vals[CB * CS * CD];

// ---------------------------------------------------------------------------
// TF32 helpers
// ---------------------------------------------------------------------------
__device__ __forceinline__ uint32_t f2tf32(float x) {
    uint32_t u;
    asm("cvt.rna.tf32.f32 %0, %1;" : "=r"(u) : "f"(x));
    return u;
}

__device__ __forceinline__ void mma_tf32(float c[4], const uint32_t a[4],
                                         const uint32_t b[2]) {
    asm volatile(
        "mma.sync.aligned.m16n8k8.row.col.f32.tf32.tf32.f32 "
        "{%0,%1,%2,%3}, {%4,%5,%6,%7}, {%8,%9}, {%0,%1,%2,%3};"
        : "+f"(c[0]), "+f"(c[1]), "+f"(c[2]), "+f"(c[3])
        : "r"(a[0]), "r"(a[1]), "r"(a[2]), "r"(a[3]), "r"(b[0]), "r"(b[1]));
}

// ---------------------------------------------------------------------------
// TF32 tensor-core GEMM, 2-stage double-buffered, batched over blockIdx.z.
// C[M,N] = A[M,K] * W[K,N]. Block tile 128x128, BK=16, 256 threads.
// ---------------------------------------------------------------------------
constexpr int BM = 128, BN = 128, BKt = 16;

__global__ __launch_bounds__(256) void sgemm_tf32_v2(
    const float* __restrict__ A0, const float* __restrict__ A1,
    const float* __restrict__ A2, const float* __restrict__ W0,
    const float* __restrict__ W1, const float* __restrict__ W2,
    float* __restrict__ C0, float* __restrict__ C1, float* __restrict__ C2,
    int M, int N, int K) {
    __shared__ uint32_t As[2][BKt][BM + 4];
    __shared__ uint32_t Bs[2][BKt][BN + 4];

    const int z = blockIdx.z;
    const float* A = (z == 0) ? A0 : (z == 1) ? A1 : A2;
    const float* W = (z == 0) ? W0 : (z == 1) ? W1 : W2;
    float*       C = (z == 0) ? C0 : (z == 1) ? C1 : C2;

    const int t    = threadIdx.x;
    const int lane = t & 31;
    const int warp = t >> 5;
    const int wm   = warp & 1;
    const int wn   = warp >> 1;
    const int gid  = lane >> 2;
    const int tg   = lane & 3;

    const int m0b = blockIdx.y * BM;
    const int n0b = blockIdx.x * BN;

    const int arow = t >> 2;
    const int acol = (t & 3) * 4;
    const int brow = t >> 4;
    const int bcol = (t & 15) * 4;

    float4 aRegs[2], bRegs[2];

    float c[4][4][4];
#pragma unroll
    for (int mt = 0; mt < 4; ++mt)
#pragma unroll
        for (int nt = 0; nt < 4; ++nt)
#pragma unroll
            for (int i = 0; i < 4; ++i) c[mt][nt][i] = 0.f;

    {
        aRegs[0] = *(const float4*)&A[(size_t)(m0b + arow) * K + acol];
        aRegs[1] = *(const float4*)&A[(size_t)(m0b + arow + 64) * K + acol];
        bRegs[0] = *(const float4*)&W[(size_t)brow * N + n0b + bcol];
        bRegs[1] = *(const float4*)&W[(size_t)brow * N + n0b + bcol + 64];
#pragma unroll
        for (int i = 0; i < 2; ++i) {
            const float* f = (const float*)&aRegs[i];
#pragma unroll
            for (int j = 0; j < 4; ++j) As[0][acol + j][arow + i * 64] = f2tf32(f[j]);
        }
#pragma unroll
        for (int i = 0; i < 2; ++i) {
            const float* f = (const float*)&bRegs[i];
#pragma unroll
            for (int j = 0; j < 4; ++j) Bs[0][brow][bcol + i * 64 + j] = f2tf32(f[j]);
        }
    }
    __syncthreads();

    int stage = 0;
    for (int k0 = 0; k0 < K; k0 += BKt) {
        const bool has_next = (k0 + BKt < K);
        if (has_next) {
            const int kn = k0 + BKt;
            aRegs[0] = *(const float4*)&A[(size_t)(m0b + arow) * K + kn + acol];
            aRegs[1] = *(const float4*)&A[(size_t)(m0b + arow + 64) * K + kn + acol];
            bRegs[0] = *(const float4*)&W[(size_t)(kn + brow) * N + n0b + bcol];
            bRegs[1] = *(const float4*)&W[(size_t)(kn + brow) * N + n0b + bcol + 64];
        }

#pragma unroll
        for (int kk = 0; kk < BKt; kk += 8) {
            uint32_t af[4][4], bf[4][2];
#pragma unroll
            for (int mt = 0; mt < 4; ++mt) {
                const int mm = wm * 64 + mt * 16 + gid;
                af[mt][0] = As[stage][kk + tg][mm];
                af[mt][1] = As[stage][kk + tg][mm + 8];
                af[mt][2] = As[stage][kk + tg + 4][mm];
                af[mt][3] = As[stage][kk + tg + 4][mm + 8];
            }
#pragma unroll
            for (int nt = 0; nt < 4; ++nt) {
                const int nn = wn * 32 + nt * 8 + gid;
                bf[nt][0] = Bs[stage][kk + tg][nn];
                bf[nt][1] = Bs[stage][kk + tg + 4][nn];
            }
#pragma unroll
            for (int mt = 0; mt < 4; ++mt)
#pragma unroll
                for (int nt = 0; nt < 4; ++nt) mma_tf32(c[mt][nt], af[mt], bf[nt]);
        }

        if (has_next) {
            const int ns = stage ^ 1;
#pragma unroll
            for (int i = 0; i < 2; ++i) {
                const float* f = (const float*)&aRegs[i];
#pragma unroll
                for (int j = 0; j < 4; ++j) As[ns][acol + j][arow + i * 64] = f2tf32(f[j]);
            }
#pragma unroll
            for (int i = 0; i < 2; ++i) {
                const float* f = (const float*)&bRegs[i];
#pragma unroll
                for (int j = 0; j < 4; ++j) Bs[ns][brow][bcol + i * 64 + j] = f2tf32(f[j]);
            }
            __syncthreads();
            stage = ns;
        }
    }

#pragma unroll
    for (int mt = 0; mt < 4; ++mt) {
        const int r0 = m0b + wm * 64 + mt * 16 + gid;
#pragma unroll
        for (int nt = 0; nt < 4; ++nt) {
            const int cc = n0b + wn * 32 + nt * 8 + tg * 2;
            *(float2*)&C[(size_t)r0 * N + cc]       = make_float2(c[mt][nt][0], c[mt][nt][1]);
            *(float2*)&C[(size_t)(r0 + 8) * N + cc] = make_float2(c[mt][nt][2], c[mt][nt][3]);
        }
    }
}

// ---------------------------------------------------------------------------
// RoPE (bf16 cos/sin tables, matching reference) + RMSNorm, in place.
// blockIdx.y selects q (0) or k (1).
// ---------------------------------------------------------------------------
__global__ __launch_bounds__(256) void rope_rms_kernel(float* __restrict__ xq,
                                                       float* __restrict__ xk) {
    float* x = blockIdx.y ? xk : xq;
    const int gt   = blockIdx.x * blockDim.x + threadIdx.x;
    const int gw   = gt >> 5;
    const int lane = gt & 31;
    if (gw >= CB * CS * CH) return;

    const int sPos = (gw / CH) % CS;
    float* p = x + (size_t)gw * CHD;

    const float x1 = p[lane];
    const float x2 = p[lane + 32];

    const float ex = (float)(2 * lane) * (1.0f / 64.0f);
    const float fr = powf(100000.0f, ex);
    const float g  = (float)sPos * (1.0f / fr);
    const float cc = __bfloat162float(__float2bfloat16(cosf(g)));
    const float sn = __bfloat162float(__float2bfloat16(sinf(g)));

    const float y1 = x1 * cc + x2 * sn;
    const float y2 = -x1 * sn + x2 * cc;

    float ss = y1 * y1 + y2 * y2;
#pragma unroll
    for (int o = 16; o > 0; o >>= 1) ss += __shfl_xor_sync(0xffffffffu, ss, o);

    const float rms = sqrtf(ss * (1.0f / 64.0f) + 1e-9f);
    const float ir  = 1.0f / rms;
    p[lane]      = y1 * ir;
    p[lane + 32] = y2 * ir;
}

// ---------------------------------------------------------------------------
// Causal flash attention with TF32 tensor cores.
// 128 q-rows per CTA (8 warps), KV tiles of 32, double-buffered KV smem,
// register prefetch, P fragments rebuilt via quad shuffles (no P smem).
// ---------------------------------------------------------------------------
__global__ __launch_bounds__(256, 2) void flash_attn_tc(
    const float* __restrict__ q, const float* __restrict__ k,
    const float* __restrict__ v, float* __restrict__ o) {
    __shared__ uint32_t Ks[2][32][68];
    __shared__ uint32_t Vs[2][32][68];

    const int t    = threadIdx.x;
    const int lane = t & 31;
    const int warp = t >> 5;
    const int gid  = lane >> 2;  // 0..7
    const int tg   = lane & 3;   // 0..3

    // heavy (late) q tiles launch first for better wave packing
    const int q0 = (gridDim.x - 1 - blockIdx.x) * 128;
    const int bh = blockIdx.y;
    const size_t base = ((size_t)(bh >> 4) * CS * CH + (bh & 15)) * CHD;
    const int rs = CH * CHD;  // 1024

    const int qrow0 = q0 + warp * 16 + gid;
    const int qrow1 = qrow0 + 8;

    // Preload Q a-fragments with the 1/sqrt(HD)=0.125 scale folded in
    // (power of two => exact, commutes with tf32 rounding).
    uint32_t qa[8][4];
#pragma unroll
    for (int ks = 0; ks < 8; ++ks) {
        qa[ks][0] = f2tf32(0.125f * q[base + (size_t)qrow0 * rs + ks * 8 + tg]);
        qa[ks][1] = f2tf32(0.125f * q[base + (size_t)qrow1 * rs + ks * 8 + tg]);
        qa[ks][2] = f2tf32(0.125f * q[base + (size_t)qrow0 * rs + ks * 8 + tg + 4]);
        qa[ks][3] = f2tf32(0.125f * q[base + (size_t)qrow1 * rs + ks * 8 + tg + 4]);
    }

    float oa[8][4];
#pragma unroll
    for (int dt = 0; dt < 8; ++dt)
#pragma unroll
        for (int i = 0; i < 4; ++i) oa[dt][i] = 0.f;

    float m0 = -1e30f, m1 = -1e30f, l0 = 0.f, l1 = 0.f;

    // prologue: fill stage 0 with KV tile 0
    {
        const int rr = t >> 6;          // 0..3 base row
        const int d  = t & 63;
#pragma unroll
        for (int j = 0; j < 8; ++j) {
            size_t gi = base + (size_t)(rr + j * 4) * rs + d;
            Ks[0][rr + j * 4][d] = f2tf32(k[gi]);
            Vs[0][rr + j * 4][d] = f2tf32(v[gi]);
        }
    }
    __syncthreads();

    const int nkt = (q0 >> 5) + 4;
    for (int kt = 0; kt < nkt; ++kt) {
        const int stage = kt & 1;
        const bool has_next = (kt + 1 < nkt);

        // prefetch next KV tile into registers (overlaps with mma below)
        float kr[8], vr[8];
        const int rr = t >> 6;
        const int d  = t & 63;
        if (has_next) {
            const int kvn = (kt + 1) << 5;
#pragma unroll
            for (int j = 0; j < 8; ++j) {
                size_t gi = base + (size_t)(kvn + rr + j * 4) * rs + d;
                kr[j] = k[gi];
                vr[j] = v[gi];
            }
        }

        const int kv0 = kt << 5;

        // ---- scores: S = (Q/8) K^T (16x32 per warp) ----
        float sc[4][4];
#pragma unroll
        for (int nt = 0; nt < 4; ++nt)
#pragma unroll
            for (int i = 0; i < 4; ++i) sc[nt][i] = 0.f;

#pragma unroll
        for (int ks = 0; ks < 8; ++ks) {
#pragma unroll
            for (int nt = 0; nt < 4; ++nt) {
                uint32_t b[2];
                b[0] = Ks[stage][nt * 8 + gid][ks * 8 + tg];
                b[1] = Ks[stage][nt * 8 + gid][ks * 8 + tg + 4];
                mma_tf32(sc[nt], qa[ks], b);
            }
        }

        // ---- causal mask ----
        const bool needmask = (kv0 + 31 > qrow0);
        if (needmask) {
#pragma unroll
            for (int nt = 0; nt < 4; ++nt) {
                const int c0 = kv0 + nt * 8 + 2 * tg;
                const int c1 = c0 + 1;
                if (c0 > qrow0) sc[nt][0] = -1e9f;
                if (c1 > qrow0) sc[nt][1] = -1e9f;
                if (c0 > qrow1) sc[nt][2] = -1e9f;
                if (c1 > qrow1) sc[nt][3] = -1e9f;
            }
        }

        // ---- online softmax (2 rows per thread, quad reductions) ----
        float tm0 = -1e30f, tm1 = -1e30f;
#pragma unroll
        for (int nt = 0; nt < 4; ++nt) {
            tm0 = fmaxf(tm0, fmaxf(sc[nt][0], sc[nt][1]));
            tm1 = fmaxf(tm1, fmaxf(sc[nt][2], sc[nt][3]));
        }
        tm0 = fmaxf(tm0, __shfl_xor_sync(0xffffffffu, tm0, 1));
        tm0 = fmaxf(tm0, __shfl_xor_sync(0xffffffffu, tm0, 2));
        tm1 = fmaxf(tm1, __shfl_xor_sync(0xffffffffu, tm1, 1));
        tm1 = fmaxf(tm1, __shfl_xor_sync(0xffffffffu, tm1, 2));

        const float m0n = fmaxf(m0, tm0);
        const float m1n = fmaxf(m1, tm1);
        const float a0  = __expf(m0 - m0n);
        const float a1  = __expf(m1 - m1n);

        uint32_t pt[4][4];  // tf32 P c-fragments
        float s0 = 0.f, s1 = 0.f;
#pragma unroll
        for (int nt = 0; nt < 4; ++nt) {
            const float p00 = __expf(sc[nt][0] - m0n);
            const float p01 = __expf(sc[nt][1] - m0n);
            const float p10 = __expf(sc[nt][2] - m1n);
            const float p11 = __expf(sc[nt][3] - m1n);
            s0 += p00 + p01;
            s1 += p10 + p11;
            pt[nt][0] = f2tf32(p00);
            pt[nt][1] = f2tf32(p01);
            pt[nt][2] = f2tf32(p10);
            pt[nt][3] = f2tf32(p11);
        }
        s0 += __shfl_xor_sync(0xffffffffu, s0, 1);
        s0 += __shfl_xor_sync(0xffffffffu, s0, 2);
        s1 += __shfl_xor_sync(0xffffffffu, s1, 1);
        s1 += __shfl_xor_sync(0xffffffffu, s1, 2);

        l0 = l0 * a0 + s0;
        l1 = l1 * a1 + s1;
        m0 = m0n;
        m1 = m1n;

#pragma unroll
        for (int dt = 0; dt < 8; ++dt) {
            oa[dt][0] *= a0;
            oa[dt][1] *= a0;
            oa[dt][2] *= a1;
            oa[dt][3] *= a1;
        }

        // ---- PV: rebuild a-fragments from c-fragments via quad shuffles ----
        const int src0 = (lane & ~3) | (tg >> 1);
        const int src2 = src0 + 2;
        const bool odd = (tg & 1);
#pragma unroll
        for (int ks2 = 0; ks2 < 4; ++ks2) {
            uint32_t a00 = __shfl_sync(0xffffffffu, pt[ks2][0], src0);
            uint32_t a01 = __shfl_sync(0xffffffffu, pt[ks2][1], src0);
            uint32_t a10 = __shfl_sync(0xffffffffu, pt[ks2][2], src0);
            uint32_t a11 = __shfl_sync(0xffffffffu, pt[ks2][3], src0);
            uint32_t b00 = __shfl_sync(0xffffffffu, pt[ks2][0], src2);
            uint32_t b01 = __shfl_sync(0xffffffffu, pt[ks2][1], src2);
            uint32_t b10 = __shfl_sync(0xffffffffu, pt[ks2][2], src2);
            uint32_t b11 = __shfl_sync(0xffffffffu, pt[ks2][3], src2);
            uint32_t pa[4];
            pa[0] = odd ? a01 : a00;
            pa[1] = odd ? a11 : a10;
            pa[2] = odd ? b01 : b00;
            pa[3] = odd ? b11 : b10;
#pragma unroll
            for (int dt = 0; dt < 8; ++dt) {
                uint32_t b[2];
                b[0] = Vs[stage][ks2 * 8 + tg][dt * 8 + gid];
                b[1] = Vs[stage][ks2 * 8 + tg + 4][dt * 8 + gid];
                mma_tf32(oa[dt], pa, b);
            }
        }

        // ---- store prefetched tile into the other stage ----
        if (has_next) {
            const int ns = stage ^ 1;
#pragma unroll
            for (int j = 0; j < 8; ++j) {
                Ks[ns][rr + j * 4][d] = f2tf32(kr[j]);
                Vs[ns][rr + j * 4][d] = f2tf32(vr[j]);
            }
        }
        __syncthreads();
    }

    // ---- epilogue ----
    const float il0 = 1.0f / l0;
    const float il1 = 1.0f / l1;
#pragma unroll
    for (int dt = 0; dt < 8; ++dt) {
        const int cc = dt * 8 + 2 * tg;
        *(float2*)&o[base + (size_t)qrow0 * rs + cc] =
            make_float2(oa[dt][0] * il0, oa[dt][1] * il0);
        *(float2*)&o[base + (size_t)qrow1 * rs + cc] =
            make_float2(oa[dt][2] * il1, oa[dt][3] * il1);
    }
}

// ---------------------------------------------------------------------------
// Launch
// ---------------------------------------------------------------------------
extern "C" void kernel_launch(void* const* d_in, const int* in_sizes, int n_in,
                              void* d_out, int out_size) {
    (void)in_sizes; (void)n_in; (void)out_size;
    const float* Q  = (const float*)d_in[0];
    const float* K  = (const float*)d_in[1];
    const float* V  = (const float*)d_in[2];
    const float* Wq = (const float*)d_in[4];
    const float* Wk = (const float*)d_in[5];
    const float* Wv = (const float*)d_in[6];
    const float* Wo = (const float*)d_in[7];
    float* out = (float*)d_out;

    float *gq, *gk, *gv, *gvals;
    cudaGetSymbolAddress((void**)&gq, g_q);
    cudaGetSymbolAddress((void**)&gk, g_k);
    cudaGetSymbolAddress((void**)&gv, g_v);
    cudaGetSymbolAddress((void**)&gvals, g_vals);

    const int M = CB * CS;               // 4096

    // Batched QKV projections
    dim3 ggrid3(CD / BN, M / BM, 3);     // (8, 32, 3)
    sgemm_tf32_v2<<<ggrid3, 256>>>(Q, K, V, Wq, Wk, Wv, gq, gk, gv, M, CD, CD);

    const int nwarps = CB * CS * CH;     // 65536
    dim3 rgrid(nwarps / 8, 2);
    rope_rms_kernel<<<rgrid, 256>>>(gq, gk);

    dim3 agrid(CS / 128, CB * CH);       // (16, 32)
    flash_attn_tc<<<agrid, 256>>>(gq, gk, gv, gvals);

    // Output projection
    dim3 ggrid1(CD / BN, M / BM, 1);
    sgemm_tf32_v2<<<ggrid1, 256>>>(gvals, nullptr, nullptr, Wo, nullptr, nullptr,
                                   out, nullptr, nullptr, M, CD, CD);
}

// round 6
// speedup vs baseline: 1.1127x; 1.0337x over previous
#include <cuda_runtime.h>
#include <cuda_bf16.h>
#include <math.h>
#include <stdint.h>

// Problem constants
constexpr int CB  = 2;
constexpr int CS  = 2048;
constexpr int CD  = 1024;
constexpr int CH  = 16;
constexpr int CHD = 64;

// Scratch (allocation-free rule: static __device__ arrays)
__device__ __align__(256) float g_q[CB * CS * CD];
__device__ __align__(256) float g_k[CB * CS * CD];
__device__ __align__(256) float g_v[CB * CS * CD];
__device__ __align__(256) float g_vals[CB * CS * CD];

// ---------------------------------------------------------------------------
// TF32 helpers
// ---------------------------------------------------------------------------
__device__ __forceinline__ uint32_t f2tf32(float x) {
    uint32_t u;
    asm("cvt.rna.tf32.f32 %0, %1;" : "=r"(u) : "f"(x));
    return u;
}

__device__ __forceinline__ void mma_tf32(float c[4], const uint32_t a[4],
                                         const uint32_t b[2]) {
    asm volatile(
        "mma.sync.aligned.m16n8k8.row.col.f32.tf32.tf32.f32 "
        "{%0,%1,%2,%3}, {%4,%5,%6,%7}, {%8,%9}, {%0,%1,%2,%3};"
        : "+f"(c[0]), "+f"(c[1]), "+f"(c[2]), "+f"(c[3])
        : "r"(a[0]), "r"(a[1]), "r"(a[2]), "r"(a[3]), "r"(b[0]), "r"(b[1]));
}

// ---------------------------------------------------------------------------
// TF32 tensor-core GEMM v3: raw-fp32 smem (STS.128 fills), cvt at fragment
// load (idle FMA pipe), conflict-free padded layouts, 2-stage double buffer.
// C[M,N] = A[M,K] * W[K,N]. Block tile 128x128, BK=16, 256 threads.
// ---------------------------------------------------------------------------
constexpr int BM = 128, BN = 128, BKt = 16;

__global__ __launch_bounds__(256) void sgemm_tf32_v3(
    const float* __restrict__ A0, const float* __restrict__ A1,
    const float* __restrict__ A2, const float* __restrict__ W0,
    const float* __restrict__ W1, const float* __restrict__ W2,
    float* __restrict__ C0, float* __restrict__ C1, float* __restrict__ C2,
    int M, int N, int K) {
    __shared__ float As[2][BM][20];    // row-major [m][k], pad 20 (conflict-free)
    __shared__ float Bs[2][BKt][136];  // [k][n], pad 136 (conflict-free)

    const int z = blockIdx.z;
    const float* A = (z == 0) ? A0 : (z == 1) ? A1 : A2;
    const float* W = (z == 0) ? W0 : (z == 1) ? W1 : W2;
    float*       C = (z == 0) ? C0 : (z == 1) ? C1 : C2;

    const int t    = threadIdx.x;
    const int lane = t & 31;
    const int warp = t >> 5;
    const int wm   = warp & 1;
    const int wn   = warp >> 1;
    const int gid  = lane >> 2;
    const int tg   = lane & 3;

    const int m0b = blockIdx.y * BM;
    const int n0b = blockIdx.x * BN;

    // fill mapping: A 128 rows x 16 cols, B 16 rows x 128 cols; 2 float4 each
    const int ar = t >> 1;          // 0..127
    const int ac = (t & 1) * 8;     // 0 or 8
    const int br = t >> 4;          // 0..15
    const int bc = (t & 15) * 8;    // 0..120

    float4 aR[2], bR[2];

    float c[4][4][4];
#pragma unroll
    for (int mt = 0; mt < 4; ++mt)
#pragma unroll
        for (int nt = 0; nt < 4; ++nt)
#pragma unroll
            for (int i = 0; i < 4; ++i) c[mt][nt][i] = 0.f;

    // prologue: fill stage 0 with tile 0 (raw fp32, STS.128)
    *(float4*)&As[0][ar][ac]     = *(const float4*)&A[(size_t)(m0b + ar) * K + ac];
    *(float4*)&As[0][ar][ac + 4] = *(const float4*)&A[(size_t)(m0b + ar) * K + ac + 4];
    *(float4*)&Bs[0][br][bc]     = *(const float4*)&W[(size_t)br * N + n0b + bc];
    *(float4*)&Bs[0][br][bc + 4] = *(const float4*)&W[(size_t)br * N + n0b + bc + 4];
    __syncthreads();

    int stage = 0;
    for (int k0 = 0; k0 < K; k0 += BKt) {
        const bool has_next = (k0 + BKt < K);
        if (has_next) {
            const int kn = k0 + BKt;
            aR[0] = *(const float4*)&A[(size_t)(m0b + ar) * K + kn + ac];
            aR[1] = *(const float4*)&A[(size_t)(m0b + ar) * K + kn + ac + 4];
            bR[0] = *(const float4*)&W[(size_t)(kn + br) * N + n0b + bc];
            bR[1] = *(const float4*)&W[(size_t)(kn + br) * N + n0b + bc + 4];
        }

#pragma unroll
        for (int kk = 0; kk < BKt; kk += 8) {
            uint32_t af[4][4], bf[4][2];
#pragma unroll
            for (int mt = 0; mt < 4; ++mt) {
                const int mm = wm * 64 + mt * 16 + gid;
                af[mt][0] = f2tf32(As[stage][mm][kk + tg]);
                af[mt][1] = f2tf32(As[stage][mm + 8][kk + tg]);
                af[mt][2] = f2tf32(As[stage][mm][kk + tg + 4]);
                af[mt][3] = f2tf32(As[stage][mm + 8][kk + tg + 4]);
            }
#pragma unroll
            for (int nt = 0; nt < 4; ++nt) {
                const int nn = wn * 32 + nt * 8 + gid;
                bf[nt][0] = f2tf32(Bs[stage][kk + tg][nn]);
                bf[nt][1] = f2tf32(Bs[stage][kk + tg + 4][nn]);
            }
#pragma unroll
            for (int mt = 0; mt < 4; ++mt)
#pragma unroll
                for (int nt = 0; nt < 4; ++nt) mma_tf32(c[mt][nt], af[mt], bf[nt]);
        }

        if (has_next) {
            const int ns = stage ^ 1;
            *(float4*)&As[ns][ar][ac]     = aR[0];
            *(float4*)&As[ns][ar][ac + 4] = aR[1];
            *(float4*)&Bs[ns][br][bc]     = bR[0];
            *(float4*)&Bs[ns][br][bc + 4] = bR[1];
            __syncthreads();
            stage = ns;
        }
    }

    // epilogue
#pragma unroll
    for (int mt = 0; mt < 4; ++mt) {
        const int r0 = m0b + wm * 64 + mt * 16 + gid;
#pragma unroll
        for (int nt = 0; nt < 4; ++nt) {
            const int cc = n0b + wn * 32 + nt * 8 + tg * 2;
            *(float2*)&C[(size_t)r0 * N + cc]       = make_float2(c[mt][nt][0], c[mt][nt][1]);
            *(float2*)&C[(size_t)(r0 + 8) * N + cc] = make_float2(c[mt][nt][2], c[mt][nt][3]);
        }
    }
}

// ---------------------------------------------------------------------------
// RoPE (bf16 cos/sin tables, matching reference) + RMSNorm, in place.
// blockIdx.y selects q (0) or k (1).
// ---------------------------------------------------------------------------
__global__ __launch_bounds__(256) void rope_rms_kernel(float* __restrict__ xq,
                                                       float* __restrict__ xk) {
    float* x = blockIdx.y ? xk : xq;
    const int gt   = blockIdx.x * blockDim.x + threadIdx.x;
    const int gw   = gt >> 5;
    const int lane = gt & 31;
    if (gw >= CB * CS * CH) return;

    const int sPos = (gw / CH) % CS;
    float* p = x + (size_t)gw * CHD;

    const float x1 = p[lane];
    const float x2 = p[lane + 32];

    const float ex = (float)(2 * lane) * (1.0f / 64.0f);
    const float fr = powf(100000.0f, ex);
    const float g  = (float)sPos * (1.0f / fr);
    const float cc = __bfloat162float(__float2bfloat16(cosf(g)));
    const float sn = __bfloat162float(__float2bfloat16(sinf(g)));

    const float y1 = x1 * cc + x2 * sn;
    const float y2 = -x1 * sn + x2 * cc;

    float ss = y1 * y1 + y2 * y2;
#pragma unroll
    for (int o = 16; o > 0; o >>= 1) ss += __shfl_xor_sync(0xffffffffu, ss, o);

    const float rms = sqrtf(ss * (1.0f / 64.0f) + 1e-9f);
    const float ir  = 1.0f / rms;
    p[lane]      = y1 * ir;
    p[lane + 32] = y2 * ir;
}

// ---------------------------------------------------------------------------
// Causal flash attention with TF32 tensor cores.
// 128 q-rows per CTA (8 warps), KV tiles of 32, double-buffered raw-fp32 KV
// smem (STS.128 fills, cvt at fragment load), register prefetch, P fragments
// rebuilt via quad shuffles (no P smem).
// ---------------------------------------------------------------------------
__global__ __launch_bounds__(256, 2) void flash_attn_tc(
    const float* __restrict__ q, const float* __restrict__ k,
    const float* __restrict__ v, float* __restrict__ o) {
    __shared__ float Ks[2][32][68];
    __shared__ float Vs[2][32][68];

    const int t    = threadIdx.x;
    const int lane = t & 31;
    const int warp = t >> 5;
    const int gid  = lane >> 2;  // 0..7
    const int tg   = lane & 3;   // 0..3

    // heavy (late) q tiles launch first for better wave packing
    const int q0 = (gridDim.x - 1 - blockIdx.x) * 128;
    const int bh = blockIdx.y;
    const size_t base = ((size_t)(bh >> 4) * CS * CH + (bh & 15)) * CHD;
    const int rs = CH * CHD;  // 1024

    const int qrow0 = q0 + warp * 16 + gid;
    const int qrow1 = qrow0 + 8;

    // fill mapping: 32 rows x 64 cols, 2 float4 per thread
    const int frr = t >> 3;         // 0..31
    const int fdc = (t & 7) * 8;    // 0..56

    // Preload Q a-fragments with the 1/sqrt(HD)=0.125 scale folded in
    // (power of two => exact, commutes with tf32 rounding).
    uint32_t qa[8][4];
#pragma unroll
    for (int ks = 0; ks < 8; ++ks) {
        qa[ks][0] = f2tf32(0.125f * q[base + (size_t)qrow0 * rs + ks * 8 + tg]);
        qa[ks][1] = f2tf32(0.125f * q[base + (size_t)qrow1 * rs + ks * 8 + tg]);
        qa[ks][2] = f2tf32(0.125f * q[base + (size_t)qrow0 * rs + ks * 8 + tg + 4]);
        qa[ks][3] = f2tf32(0.125f * q[base + (size_t)qrow1 * rs + ks * 8 + tg + 4]);
    }

    float oa[8][4];
#pragma unroll
    for (int dt = 0; dt < 8; ++dt)
#pragma unroll
        for (int i = 0; i < 4; ++i) oa[dt][i] = 0.f;

    float m0 = -1e30f, m1 = -1e30f, l0 = 0.f, l1 = 0.f;

    // prologue: fill stage 0 with KV tile 0
    {
        const size_t gi = base + (size_t)frr * rs + fdc;
        *(float4*)&Ks[0][frr][fdc]     = *(const float4*)&k[gi];
        *(float4*)&Ks[0][frr][fdc + 4] = *(const float4*)&k[gi + 4];
        *(float4*)&Vs[0][frr][fdc]     = *(const float4*)&v[gi];
        *(float4*)&Vs[0][frr][fdc + 4] = *(const float4*)&v[gi + 4];
    }
    __syncthreads();

    const int nkt = (q0 >> 5) + 4;
    for (int kt = 0; kt < nkt; ++kt) {
        const int stage = kt & 1;
        const bool has_next = (kt + 1 < nkt);

        // prefetch next KV tile into registers (overlaps with mma below)
        float4 kr0, kr1, vr0, vr1;
        if (has_next) {
            const size_t gi = base + (size_t)(((kt + 1) << 5) + frr) * rs + fdc;
            kr0 = *(const float4*)&k[gi];
            kr1 = *(const float4*)&k[gi + 4];
            vr0 = *(const float4*)&v[gi];
            vr1 = *(const float4*)&v[gi + 4];
        }

        const int kv0 = kt << 5;

        // ---- scores: S = (Q/8) K^T (16x32 per warp) ----
        float sc[4][4];
#pragma unroll
        for (int nt = 0; nt < 4; ++nt)
#pragma unroll
            for (int i = 0; i < 4; ++i) sc[nt][i] = 0.f;

#pragma unroll
        for (int ks = 0; ks < 8; ++ks) {
#pragma unroll
            for (int nt = 0; nt < 4; ++nt) {
                uint32_t b[2];
                b[0] = f2tf32(Ks[stage][nt * 8 + gid][ks * 8 + tg]);
                b[1] = f2tf32(Ks[stage][nt * 8 + gid][ks * 8 + tg + 4]);
                mma_tf32(sc[nt], qa[ks], b);
            }
        }

        // ---- causal mask ----
        const bool needmask = (kv0 + 31 > qrow0);
        if (needmask) {
#pragma unroll
            for (int nt = 0; nt < 4; ++nt) {
                const int c0 = kv0 + nt * 8 + 2 * tg;
                const int c1 = c0 + 1;
                if (c0 > qrow0) sc[nt][0] = -1e9f;
                if (c1 > qrow0) sc[nt][1] = -1e9f;
                if (c0 > qrow1) sc[nt][2] = -1e9f;
                if (c1 > qrow1) sc[nt][3] = -1e9f;
            }
        }

        // ---- online softmax (2 rows per thread, quad reductions) ----
        float tm0 = -1e30f, tm1 = -1e30f;
#pragma unroll
        for (int nt = 0; nt < 4; ++nt) {
            tm0 = fmaxf(tm0, fmaxf(sc[nt][0], sc[nt][1]));
            tm1 = fmaxf(tm1, fmaxf(sc[nt][2], sc[nt][3]));
        }
        tm0 = fmaxf(tm0, __shfl_xor_sync(0xffffffffu, tm0, 1));
        tm0 = fmaxf(tm0, __shfl_xor_sync(0xffffffffu, tm0, 2));
        tm1 = fmaxf(tm1, __shfl_xor_sync(0xffffffffu, tm1, 1));
        tm1 = fmaxf(tm1, __shfl_xor_sync(0xffffffffu, tm1, 2));

        const float m0n = fmaxf(m0, tm0);
        const float m1n = fmaxf(m1, tm1);
        const float a0  = __expf(m0 - m0n);
        const float a1  = __expf(m1 - m1n);

        uint32_t pt[4][4];  // tf32 P c-fragments
        float s0 = 0.f, s1 = 0.f;
#pragma unroll
        for (int nt = 0; nt < 4; ++nt) {
            const float p00 = __expf(sc[nt][0] - m0n);
            const float p01 = __expf(sc[nt][1] - m0n);
            const float p10 = __expf(sc[nt][2] - m1n);
            const float p11 = __expf(sc[nt][3] - m1n);
            s0 += p00 + p01;
            s1 += p10 + p11;
            pt[nt][0] = f2tf32(p00);
            pt[nt][1] = f2tf32(p01);
            pt[nt][2] = f2tf32(p10);
            pt[nt][3] = f2tf32(p11);
        }
        s0 += __shfl_xor_sync(0xffffffffu, s0, 1);
        s0 += __shfl_xor_sync(0xffffffffu, s0, 2);
        s1 += __shfl_xor_sync(0xffffffffu, s1, 1);
        s1 += __shfl_xor_sync(0xffffffffu, s1, 2);

        l0 = l0 * a0 + s0;
        l1 = l1 * a1 + s1;
        m0 = m0n;
        m1 = m1n;

#pragma unroll
        for (int dt = 0; dt < 8; ++dt) {
            oa[dt][0] *= a0;
            oa[dt][1] *= a0;
            oa[dt][2] *= a1;
            oa[dt][3] *= a1;
        }

        // ---- PV: rebuild a-fragments from c-fragments via quad shuffles ----
        const int src0 = (lane & ~3) | (tg >> 1);
        const int src2 = src0 + 2;
        const bool odd = (tg & 1);
#pragma unroll
        for (int ks2 = 0; ks2 < 4; ++ks2) {
            uint32_t a00 = __shfl_sync(0xffffffffu, pt[ks2][0], src0);
            uint32_t a01 = __shfl_sync(0xffffffffu, pt[ks2][1], src0);
            uint32_t a10 = __shfl_sync(0xffffffffu, pt[ks2][2], src0);
            uint32_t a11 = __shfl_sync(0xffffffffu, pt[ks2][3], src0);
            uint32_t b00 = __shfl_sync(0xffffffffu, pt[ks2][0], src2);
            uint32_t b01 = __shfl_sync(0xffffffffu, pt[ks2][1], src2);
            uint32_t b10 = __shfl_sync(0xffffffffu, pt[ks2][2], src2);
            uint32_t b11 = __shfl_sync(0xffffffffu, pt[ks2][3], src2);
            uint32_t pa[4];
            pa[0] = odd ? a01 : a00;
            pa[1] = odd ? a11 : a10;
            pa[2] = odd ? b01 : b00;
            pa[3] = odd ? b11 : b10;
#pragma unroll
            for (int dt = 0; dt < 8; ++dt) {
                uint32_t b[2];
                b[0] = f2tf32(Vs[stage][ks2 * 8 + tg][dt * 8 + gid]);
                b[1] = f2tf32(Vs[stage][ks2 * 8 + tg + 4][dt * 8 + gid]);
                mma_tf32(oa[dt], pa, b);
            }
        }

        // ---- store prefetched tile into the other stage ----
        if (has_next) {
            const int ns = stage ^ 1;
            *(float4*)&Ks[ns][frr][fdc]     = kr0;
            *(float4*)&Ks[ns][frr][fdc + 4] = kr1;
            *(float4*)&Vs[ns][frr][fdc]     = vr0;
            *(float4*)&Vs[ns][frr][fdc + 4] = vr1;
        }
        __syncthreads();
    }

    // ---- epilogue ----
    const float il0 = 1.0f / l0;
    const float il1 = 1.0f / l1;
#pragma unroll
    for (int dt = 0; dt < 8; ++dt) {
        const int cc = dt * 8 + 2 * tg;
        *(float2*)&o[base + (size_t)qrow0 * rs + cc] =
            make_float2(oa[dt][0] * il0, oa[dt][1] * il0);
        *(float2*)&o[base + (size_t)qrow1 * rs + cc] =
            make_float2(oa[dt][2] * il1, oa[dt][3] * il1);
    }
}

// ---------------------------------------------------------------------------
// Launch
// ---------------------------------------------------------------------------
extern "C" void kernel_launch(void* const* d_in, const int* in_sizes, int n_in,
                              void* d_out, int out_size) {
    (void)in_sizes; (void)n_in; (void)out_size;
    const float* Q  = (const float*)d_in[0];
    const float* K  = (const float*)d_in[1];
    const float* V  = (const float*)d_in[2];
    const float* Wq = (const float*)d_in[4];
    const float* Wk = (const float*)d_in[5];
    const float* Wv = (const float*)d_in[6];
    const float* Wo = (const float*)d_in[7];
    float* out = (float*)d_out;

    float *gq, *gk, *gv, *gvals;
    cudaGetSymbolAddress((void**)&gq, g_q);
    cudaGetSymbolAddress((void**)&gk, g_k);
    cudaGetSymbolAddress((void**)&gv, g_v);
    cudaGetSymbolAddress((void**)&gvals, g_vals);

    const int M = CB * CS;               // 4096

    // Batched QKV projections
    dim3 ggrid3(CD / BN, M / BM, 3);     // (8, 32, 3)
    sgemm_tf32_v3<<<ggrid3, 256>>>(Q, K, V, Wq, Wk, Wv, gq, gk, gv, M, CD, CD);

    const int nwarps = CB * CS * CH;     // 65536
    dim3 rgrid(nwarps / 8, 2);
    rope_rms_kernel<<<rgrid, 256>>>(gq, gk);

    dim3 agrid(CS / 128, CB * CH);       // (16, 32)
    flash_attn_tc<<<agrid, 256>>>(gq, gk, gv, gvals);

    // Output projection
    dim3 ggrid1(CD / BN, M / BM, 1);
    sgemm_tf32_v3<<<ggrid1, 256>>>(gvals, nullptr, nullptr, Wo, nullptr, nullptr,
                                   out, nullptr, nullptr, M, CD, CD);
}

// round 8
// speedup vs baseline: 1.2158x; 1.0926x over previous
#include <cuda_runtime.h>
#include <cuda_bf16.h>
#include <math.h>
#include <stdint.h>

// Problem constants
constexpr int CB  = 2;
constexpr int CS  = 2048;
constexpr int CD  = 1024;
constexpr int CH  = 16;
constexpr int CHD = 64;
constexpr int MT  = CB * CS;  // 4096

// Scratch (allocation-free rule: static __device__ arrays)
__device__ __align__(256) float g_q[MT * CD];
__device__ __align__(256) float g_k[MT * CD];
__device__ __align__(256) float g_v[MT * CD];
__device__ __align__(256) float g_vals[MT * CD];

// ---------------------------------------------------------------------------
// TF32 helpers
// ---------------------------------------------------------------------------
__device__ __forceinline__ uint32_t f2tf32(float x) {
    uint32_t u;
    asm("cvt.rna.tf32.f32 %0, %1;" : "=r"(u) : "f"(x));
    return u;
}

__device__ __forceinline__ void mma_tf32(float c[4], const uint32_t a[4],
                                         const uint32_t b[2]) {
    asm volatile(
        "mma.sync.aligned.m16n8k8.row.col.f32.tf32.tf32.f32 "
        "{%0,%1,%2,%3}, {%4,%5,%6,%7}, {%8,%9}, {%0,%1,%2,%3};"
        : "+f"(c[0]), "+f"(c[1]), "+f"(c[2]), "+f"(c[3])
        : "r"(a[0]), "r"(a[1]), "r"(a[2]), "r"(a[3]), "r"(b[0]), "r"(b[1]));
}

// ---------------------------------------------------------------------------
// TF32 tensor-core GEMM v4: 128 threads (4 warps), warp tile 64x64
// (higher MAC/LDS-byte), raw-fp32 smem with STS.128 fills, cvt at fragment
// load, 2-stage double buffer. C[M,N] = A[M,K] * W[K,N]. CTA tile 128x128.
// ---------------------------------------------------------------------------
constexpr int BM = 128, BN = 128, BKt = 16;

__global__ __launch_bounds__(128) void sgemm_tf32_v4(
    const float* __restrict__ A0, const float* __restrict__ A1,
    const float* __restrict__ A2, const float* __restrict__ W0,
    const float* __restrict__ W1, const float* __restrict__ W2,
    float* __restrict__ C0, float* __restrict__ C1, float* __restrict__ C2,
    int M, int N, int K) {
    __shared__ float As[2][BM][20];    // [m][k], pad 20
    __shared__ float Bs[2][BKt][136];  // [k][n], pad 136

    const int z = blockIdx.z;
    const float* A = (z == 0) ? A0 : (z == 1) ? A1 : A2;
    const float* W = (z == 0) ? W0 : (z == 1) ? W1 : W2;
    float*       C = (z == 0) ? C0 : (z == 1) ? C1 : C2;

    const int t    = threadIdx.x;
    const int lane = t & 31;
    const int warp = t >> 5;
    const int wm   = warp & 1;   // 0..1 -> m offset 0/64
    const int wn   = warp >> 1;  // 0..1 -> n offset 0/64
    const int gid  = lane >> 2;  // 0..7
    const int tg   = lane & 3;   // 0..3

    const int m0b = blockIdx.y * BM;
    const int n0b = blockIdx.x * BN;

    // fill mappings (4 float4 each for A and B)
    // A: idx = t + i*128 -> row idx>>2 (0..127), col (idx&3)*4
    // B: idx = t + i*128 -> row idx>>5 (0..15), col (idx&31)*4
    float4 aR[4], bR[4];

    float c[4][8][4];
#pragma unroll
    for (int mt = 0; mt < 4; ++mt)
#pragma unroll
        for (int nt = 0; nt < 8; ++nt)
#pragma unroll
            for (int i = 0; i < 4; ++i) c[mt][nt][i] = 0.f;

    // prologue: fill stage 0 with tile 0
#pragma unroll
    for (int i = 0; i < 4; ++i) {
        const int ia = t + i * 128;
        const int ar = ia >> 2, ac = (ia & 3) * 4;
        *(float4*)&As[0][ar][ac] = *(const float4*)&A[(size_t)(m0b + ar) * K + ac];
        const int br = ia >> 5, bc = (ia & 31) * 4;
        *(float4*)&Bs[0][br][bc] = *(const float4*)&W[(size_t)br * N + n0b + bc];
    }
    __syncthreads();

    int stage = 0;
    for (int k0 = 0; k0 < K; k0 += BKt) {
        const bool has_next = (k0 + BKt < K);
        if (has_next) {
            const int kn = k0 + BKt;
#pragma unroll
            for (int i = 0; i < 4; ++i) {
                const int ia = t + i * 128;
                const int ar = ia >> 2, ac = (ia & 3) * 4;
                aR[i] = *(const float4*)&A[(size_t)(m0b + ar) * K + kn + ac];
                const int br = ia >> 5, bc = (ia & 31) * 4;
                bR[i] = *(const float4*)&W[(size_t)(kn + br) * N + n0b + bc];
            }
        }

#pragma unroll
        for (int kk = 0; kk < BKt; kk += 8) {
            uint32_t af[4][4], bf[8][2];
#pragma unroll
            for (int mt = 0; mt < 4; ++mt) {
                const int mm = wm * 64 + mt * 16 + gid;
                af[mt][0] = f2tf32(As[stage][mm][kk + tg]);
                af[mt][1] = f2tf32(As[stage][mm + 8][kk + tg]);
                af[mt][2] = f2tf32(As[stage][mm][kk + tg + 4]);
                af[mt][3] = f2tf32(As[stage][mm + 8][kk + tg + 4]);
            }
#pragma unroll
            for (int nt = 0; nt < 8; ++nt) {
                const int nn = wn * 64 + nt * 8 + gid;
                bf[nt][0] = f2tf32(Bs[stage][kk + tg][nn]);
                bf[nt][1] = f2tf32(Bs[stage][kk + tg + 4][nn]);
            }
#pragma unroll
            for (int mt = 0; mt < 4; ++mt)
#pragma unroll
                for (int nt = 0; nt < 8; ++nt) mma_tf32(c[mt][nt], af[mt], bf[nt]);
        }

        if (has_next) {
            const int ns = stage ^ 1;
#pragma unroll
            for (int i = 0; i < 4; ++i) {
                const int ia = t + i * 128;
                const int ar = ia >> 2, ac = (ia & 3) * 4;
                *(float4*)&As[ns][ar][ac] = aR[i];
                const int br = ia >> 5, bc = (ia & 31) * 4;
                *(float4*)&Bs[ns][br][bc] = bR[i];
            }
            __syncthreads();
            stage = ns;
        }
    }

    // epilogue
#pragma unroll
    for (int mt = 0; mt < 4; ++mt) {
        const int r0 = m0b + wm * 64 + mt * 16 + gid;
#pragma unroll
        for (int nt = 0; nt < 8; ++nt) {
            const int cc = n0b + wn * 64 + nt * 8 + tg * 2;
            *(float2*)&C[(size_t)r0 * N + cc]       = make_float2(c[mt][nt][0], c[mt][nt][1]);
            *(float2*)&C[(size_t)(r0 + 8) * N + cc] = make_float2(c[mt][nt][2], c[mt][nt][3]);
        }
    }
}

// ---------------------------------------------------------------------------
// RoPE (bf16 cos/sin tables, matching reference) + RMSNorm, in place.
// blockIdx.y selects q (0) or k (1).
// ---------------------------------------------------------------------------
__global__ __launch_bounds__(256) void rope_rms_kernel(float* __restrict__ xq,
                                                       float* __restrict__ xk) {
    float* x = blockIdx.y ? xk : xq;
    const int gt   = blockIdx.x * blockDim.x + threadIdx.x;
    const int gw   = gt >> 5;
    const int lane = gt & 31;
    if (gw >= CB * CS * CH) return;

    const int sPos = (gw / CH) % CS;
    float* p = x + (size_t)gw * CHD;

    const float x1 = p[lane];
    const float x2 = p[lane + 32];

    const float ex = (float)(2 * lane) * (1.0f / 64.0f);
    const float fr = powf(100000.0f, ex);
    const float g  = (float)sPos * (1.0f / fr);
    const float cc = __bfloat162float(__float2bfloat16(cosf(g)));
    const float sn = __bfloat162float(__float2bfloat16(sinf(g)));

    const float y1 = x1 * cc + x2 * sn;
    const float y2 = -x1 * sn + x2 * cc;

    float ss = y1 * y1 + y2 * y2;
#pragma unroll
    for (int o = 16; o > 0; o >>= 1) ss += __shfl_xor_sync(0xffffffffu, ss, o);

    const float rms = sqrtf(ss * (1.0f / 64.0f) + 1e-9f);
    const float ir  = 1.0f / rms;
    p[lane]      = y1 * ir;
    p[lane + 32] = y2 * ir;
}

// ---------------------------------------------------------------------------
// Causal flash attention with TF32 tensor cores (unchanged from R6 best).
// ---------------------------------------------------------------------------
__global__ __launch_bounds__(256, 2) void flash_attn_tc(
    const float* __restrict__ q, const float* __restrict__ k,
    const float* __restrict__ v, float* __restrict__ o) {
    __shared__ float Ks[2][32][68];
    __shared__ float Vs[2][32][68];

    const int t    = threadIdx.x;
    const int lane = t & 31;
    const int warp = t >> 5;
    const int gid  = lane >> 2;
    const int tg   = lane & 3;

    const int q0 = (gridDim.x - 1 - blockIdx.x) * 128;
    const int bh = blockIdx.y;
    const size_t base = ((size_t)(bh >> 4) * CS * CH + (bh & 15)) * CHD;
    const int rs = CH * CHD;

    const int qrow0 = q0 + warp * 16 + gid;
    const int qrow1 = qrow0 + 8;

    const int frr = t >> 3;
    const int fdc = (t & 7) * 8;

    uint32_t qa[8][4];
#pragma unroll
    for (int ks = 0; ks < 8; ++ks) {
        qa[ks][0] = f2tf32(0.125f * q[base + (size_t)qrow0 * rs + ks * 8 + tg]);
        qa[ks][1] = f2tf32(0.125f * q[base + (size_t)qrow1 * rs + ks * 8 + tg]);
        qa[ks][2] = f2tf32(0.125f * q[base + (size_t)qrow0 * rs + ks * 8 + tg + 4]);
        qa[ks][3] = f2tf32(0.125f * q[base + (size_t)qrow1 * rs + ks * 8 + tg + 4]);
    }

    float oa[8][4];
#pragma unroll
    for (int dt = 0; dt < 8; ++dt)
#pragma unroll
        for (int i = 0; i < 4; ++i) oa[dt][i] = 0.f;

    float m0 = -1e30f, m1 = -1e30f, l0 = 0.f, l1 = 0.f;

    {
        const size_t gi = base + (size_t)frr * rs + fdc;
        *(float4*)&Ks[0][frr][fdc]     = *(const float4*)&k[gi];
        *(float4*)&Ks[0][frr][fdc + 4] = *(const float4*)&k[gi + 4];
        *(float4*)&Vs[0][frr][fdc]     = *(const float4*)&v[gi];
        *(float4*)&Vs[0][frr][fdc + 4] = *(const float4*)&v[gi + 4];
    }
    __syncthreads();

    const int nkt = (q0 >> 5) + 4;
    for (int kt = 0; kt < nkt; ++kt) {
        const int stage = kt & 1;
        const bool has_next = (kt + 1 < nkt);

        float4 kr0, kr1, vr0, vr1;
        if (has_next) {
            const size_t gi = base + (size_t)(((kt + 1) << 5) + frr) * rs + fdc;
            kr0 = *(const float4*)&k[gi];
            kr1 = *(const float4*)&k[gi + 4];
            vr0 = *(const float4*)&v[gi];
            vr1 = *(const float4*)&v[gi + 4];
        }

        const int kv0 = kt << 5;

        float sc[4][4];
#pragma unroll
        for (int nt = 0; nt < 4; ++nt)
#pragma unroll
            for (int i = 0; i < 4; ++i) sc[nt][i] = 0.f;

#pragma unroll
        for (int ks = 0; ks < 8; ++ks) {
#pragma unroll
            for (int nt = 0; nt < 4; ++nt) {
                uint32_t b[2];
                b[0] = f2tf32(Ks[stage][nt * 8 + gid][ks * 8 + tg]);
                b[1] = f2tf32(Ks[stage][nt * 8 + gid][ks * 8 + tg + 4]);
                mma_tf32(sc[nt], qa[ks], b);
            }
        }

        const bool needmask = (kv0 + 31 > qrow0);
        if (needmask) {
#pragma unroll
            for (int nt = 0; nt < 4; ++nt) {
                const int c0 = kv0 + nt * 8 + 2 * tg;
                const int c1 = c0 + 1;
                if (c0 > qrow0) sc[nt][0] = -1e9f;
                if (c1 > qrow0) sc[nt][1] = -1e9f;
                if (c0 > qrow1) sc[nt][2] = -1e9f;
                if (c1 > qrow1) sc[nt][3] = -1e9f;
            }
        }

        float tm0 = -1e30f, tm1 = -1e30f;
#pragma unroll
        for (int nt = 0; nt < 4; ++nt) {
            tm0 = fmaxf(tm0, fmaxf(sc[nt][0], sc[nt][1]));
            tm1 = fmaxf(tm1, fmaxf(sc[nt][2], sc[nt][3]));
        }
        tm0 = fmaxf(tm0, __shfl_xor_sync(0xffffffffu, tm0, 1));
        tm0 = fmaxf(tm0, __shfl_xor_sync(0xffffffffu, tm0, 2));
        tm1 = fmaxf(tm1, __shfl_xor_sync(0xffffffffu, tm1, 1));
        tm1 = fmaxf(tm1, __shfl_xor_sync(0xffffffffu, tm1, 2));

        const float m0n = fmaxf(m0, tm0);
        const float m1n = fmaxf(m1, tm1);
        const float a0  = __expf(m0 - m0n);
        const float a1  = __expf(m1 - m1n);

        uint32_t pt[4][4];
        float s0 = 0.f, s1 = 0.f;
#pragma unroll
        for (int nt = 0; nt < 4; ++nt) {
            const float p00 = __expf(sc[nt][0] - m0n);
            const float p01 = __expf(sc[nt][1] - m0n);
            const float p10 = __expf(sc[nt][2] - m1n);
            const float p11 = __expf(sc[nt][3] - m1n);
            s0 += p00 + p01;
            s1 += p10 + p11;
            pt[nt][0] = f2tf32(p00);
            pt[nt][1] = f2tf32(p01);
            pt[nt][2] = f2tf32(p10);
            pt[nt][3] = f2tf32(p11);
        }
        s0 += __shfl_xor_sync(0xffffffffu, s0, 1);
        s0 += __shfl_xor_sync(0xffffffffu, s0, 2);
        s1 += __shfl_xor_sync(0xffffffffu, s1, 1);
        s1 += __shfl_xor_sync(0xffffffffu, s1, 2);

        l0 = l0 * a0 + s0;
        l1 = l1 * a1 + s1;
        m0 = m0n;
        m1 = m1n;

#pragma unroll
        for (int dt = 0; dt < 8; ++dt) {
            oa[dt][0] *= a0;
            oa[dt][1] *= a0;
            oa[dt][2] *= a1;
            oa[dt][3] *= a1;
        }

        const int src0 = (lane & ~3) | (tg >> 1);
        const int src2 = src0 + 2;
        const bool odd = (tg & 1);
#pragma unroll
        for (int ks2 = 0; ks2 < 4; ++ks2) {
            uint32_t a00 = __shfl_sync(0xffffffffu, pt[ks2][0], src0);
            uint32_t a01 = __shfl_sync(0xffffffffu, pt[ks2][1], src0);
            uint32_t a10 = __shfl_sync(0xffffffffu, pt[ks2][2], src0);
            uint32_t a11 = __shfl_sync(0xffffffffu, pt[ks2][3], src0);
            uint32_t b00 = __shfl_sync(0xffffffffu, pt[ks2][0], src2);
            uint32_t b01 = __shfl_sync(0xffffffffu, pt[ks2][1], src2);
            uint32_t b10 = __shfl_sync(0xffffffffu, pt[ks2][2], src2);
            uint32_t b11 = __shfl_sync(0xffffffffu, pt[ks2][3], src2);
            uint32_t pa[4];
            pa[0] = odd ? a01 : a00;
            pa[1] = odd ? a11 : a10;
            pa[2] = odd ? b01 : b00;
            pa[3] = odd ? b11 : b10;
#pragma unroll
            for (int dt = 0; dt < 8; ++dt) {
                uint32_t b[2];
                b[0] = f2tf32(Vs[stage][ks2 * 8 + tg][dt * 8 + gid]);
                b[1] = f2tf32(Vs[stage][ks2 * 8 + tg + 4][dt * 8 + gid]);
                mma_tf32(oa[dt], pa, b);
            }
        }

        if (has_next) {
            const int ns = stage ^ 1;
            *(float4*)&Ks[ns][frr][fdc]     = kr0;
            *(float4*)&Ks[ns][frr][fdc + 4] = kr1;
            *(float4*)&Vs[ns][frr][fdc]     = vr0;
            *(float4*)&Vs[ns][frr][fdc + 4] = vr1;
        }
        __syncthreads();
    }

    const float il0 = 1.0f / l0;
    const float il1 = 1.0f / l1;
#pragma unroll
    for (int dt = 0; dt < 8; ++dt) {
        const int cc = dt * 8 + 2 * tg;
        *(float2*)&o[base + (size_t)qrow0 * rs + cc] =
            make_float2(oa[dt][0] * il0, oa[dt][1] * il0);
        *(float2*)&o[base + (size_t)qrow1 * rs + cc] =
            make_float2(oa[dt][2] * il1, oa[dt][3] * il1);
    }
}

// ---------------------------------------------------------------------------
// Launch
// ---------------------------------------------------------------------------
extern "C" void kernel_launch(void* const* d_in, const int* in_sizes, int n_in,
                              void* d_out, int out_size) {
    (void)in_sizes; (void)n_in; (void)out_size;
    const float* Q  = (const float*)d_in[0];
    const float* K  = (const float*)d_in[1];
    const float* V  = (const float*)d_in[2];
    const float* Wq = (const float*)d_in[4];
    const float* Wk = (const float*)d_in[5];
    const float* Wv = (const float*)d_in[6];
    const float* Wo = (const float*)d_in[7];
    float* out = (float*)d_out;

    float *gq, *gk, *gv, *gvals;
    cudaGetSymbolAddress((void**)&gq, g_q);
    cudaGetSymbolAddress((void**)&gk, g_k);
    cudaGetSymbolAddress((void**)&gv, g_v);
    cudaGetSymbolAddress((void**)&gvals, g_vals);

    const int M = MT;  // 4096

    // Batched QKV projections
    dim3 ggrid3(CD / BN, M / BM, 3);     // (8, 32, 3)
    sgemm_tf32_v4<<<ggrid3, 128>>>(Q, K, V, Wq, Wk, Wv, gq, gk, gv, M, CD, CD);

    const int nwarps = CB * CS * CH;     // 65536
    dim3 rgrid(nwarps / 8, 2);
    rope_rms_kernel<<<rgrid, 256>>>(gq, gk);

    dim3 agrid(CS / 128, CB * CH);       // (16, 32)
    flash_attn_tc<<<agrid, 256>>>(gq, gk, gv, gvals);

    // Output projection
    dim3 ggrid1(CD / BN, M / BM, 1);
    sgemm_tf32_v4<<<ggrid1, 128>>>(gvals, nullptr, nullptr, Wo, nullptr, nullptr,
                                   out, nullptr, nullptr, M, CD, CD);
}

// round 9
// speedup vs baseline: 1.2576x; 1.0343x over previous
#include <cuda_runtime.h>
#include <cuda_bf16.h>
#include <math.h>
#include <stdint.h>

// Problem constants
constexpr int CB  = 2;
constexpr int CS  = 2048;
constexpr int CD  = 1024;
constexpr int CH  = 16;
constexpr int CHD = 64;
constexpr int MT  = CB * CS;  // 4096

// Scratch (allocation-free rule: static __device__ arrays)
__device__ __align__(256) float g_q[MT * CD];
__device__ __align__(256) float g_k[MT * CD];
__device__ __align__(256) float g_v[MT * CD];
__device__ __align__(256) float g_vals[MT * CD];

// ---------------------------------------------------------------------------
// TF32 helpers
// ---------------------------------------------------------------------------
__device__ __forceinline__ uint32_t f2tf32(float x) {
    uint32_t u;
    asm("cvt.rna.tf32.f32 %0, %1;" : "=r"(u) : "f"(x));
    return u;
}

__device__ __forceinline__ void mma_tf32(float c[4], const uint32_t a[4],
                                         const uint32_t b[2]) {
    asm volatile(
        "mma.sync.aligned.m16n8k8.row.col.f32.tf32.tf32.f32 "
        "{%0,%1,%2,%3}, {%4,%5,%6,%7}, {%8,%9}, {%0,%1,%2,%3};"
        : "+f"(c[0]), "+f"(c[1]), "+f"(c[2]), "+f"(c[3])
        : "r"(a[0]), "r"(a[1]), "r"(a[2]), "r"(a[3]), "r"(b[0]), "r"(b[1]));
}

__device__ __forceinline__ uint32_t smem_u32(const void* p) {
    uint32_t a;
    asm("{ .reg .u64 t; cvta.to.shared.u64 t, %1; cvt.u32.u64 %0, t; }"
        : "=r"(a) : "l"(p));
    return a;
}

__device__ __forceinline__ void cp16(uint32_t dst, const void* src) {
    asm volatile("cp.async.cg.shared.global [%0], [%1], 16;"
                 :: "r"(dst), "l"(src) : "memory");
}
#define CP_COMMIT() asm volatile("cp.async.commit_group;" ::: "memory")
#define CP_WAIT1()  asm volatile("cp.async.wait_group 1;" ::: "memory")

// ---------------------------------------------------------------------------
// TF32 tensor-core GEMM v5: cp.async 3-stage pipeline, BK=32, dynamic smem,
// 128 threads (4 warps, 64x64 warp tiles), raw-fp32 smem, cvt at fragment
// load. C[M,N] = A[M,K] * W[K,N]. CTA tile 128x128.
// ---------------------------------------------------------------------------
constexpr int BM = 128, BN = 128;
constexpr int APAD = 36;                         // words per A row (k32 + pad)
constexpr int BPAD = 136;                        // words per B row (n128 + pad)
constexpr int ABYTES = BM * APAD * 4;            // 18432
constexpr int BBYTES = 32 * BPAD * 4;            // 17408
constexpr int STAGEB = ABYTES + BBYTES;          // 35840
constexpr int GEMM_SMEM5 = 3 * STAGEB;           // 107520

__global__ __launch_bounds__(128) void sgemm_tf32_v5(
    const float* __restrict__ A0, const float* __restrict__ A1,
    const float* __restrict__ A2, const float* __restrict__ W0,
    const float* __restrict__ W1, const float* __restrict__ W2,
    float* __restrict__ C0, float* __restrict__ C1, float* __restrict__ C2,
    int M, int N, int K) {
    extern __shared__ char smem[];
    const uint32_t sb = smem_u32(smem);

    const int z = blockIdx.z;
    const float* A = (z == 0) ? A0 : (z == 1) ? A1 : A2;
    const float* W = (z == 0) ? W0 : (z == 1) ? W1 : W2;
    float*       C = (z == 0) ? C0 : (z == 1) ? C1 : C2;

    const int t    = threadIdx.x;
    const int lane = t & 31;
    const int warp = t >> 5;
    const int wm   = warp & 1;   // m offset 0/64
    const int wn   = warp >> 1;  // n offset 0/64
    const int gid  = lane >> 2;  // 0..7
    const int tg   = lane & 3;   // 0..3

    const int m0b = blockIdx.y * BM;
    const int n0b = blockIdx.x * BN;

    const int NC = K / 32;  // 32 chunks

    float c[4][8][4];
#pragma unroll
    for (int mt = 0; mt < 4; ++mt)
#pragma unroll
        for (int nt = 0; nt < 8; ++nt)
#pragma unroll
            for (int i = 0; i < 4; ++i) c[mt][nt][i] = 0.f;

    // async fill of one stage: A 128x32 fp32 (1024 16B chunks) +
    //                          B  32x128 fp32 (1024 16B chunks)
    auto issue = [&](int ck, int s) {
        const int kn = ck * 32;
        const uint32_t abase = sb + s * STAGEB;
        const uint32_t bbase = abase + ABYTES;
#pragma unroll
        for (int i = 0; i < 8; ++i) {
            const int ci = t + i * 128;
            const int ar = ci >> 3, as = ci & 7;  // row 0..127, 16B seg 0..7
            cp16(abase + (ar * APAD + as * 4) * 4,
                 &A[(size_t)(m0b + ar) * K + kn + as * 4]);
            const int br = ci >> 5, bs = ci & 31;  // row 0..31, seg 0..31
            cp16(bbase + (br * BPAD + bs * 4) * 4,
                 &W[(size_t)(kn + br) * N + n0b + bs * 4]);
        }
        CP_COMMIT();
    };

    issue(0, 0);
    issue(1, 1);

    for (int ck = 0; ck < NC; ++ck) {
        CP_WAIT1();
        __syncthreads();  // all warps done with compute(ck-1); stage ck visible
        if (ck + 2 < NC) issue(ck + 2, (ck + 2) % 3);

        const int s = ck % 3;
        const float* As = (const float*)(smem + s * STAGEB);
        const float* Bs = (const float*)(smem + s * STAGEB + ABYTES);

#pragma unroll
        for (int kk = 0; kk < 32; kk += 8) {
            uint32_t af[4][4], bf[8][2];
#pragma unroll
            for (int mt = 0; mt < 4; ++mt) {
                const int mm = wm * 64 + mt * 16 + gid;
                af[mt][0] = f2tf32(As[mm * APAD + kk + tg]);
                af[mt][1] = f2tf32(As[(mm + 8) * APAD + kk + tg]);
                af[mt][2] = f2tf32(As[mm * APAD + kk + tg + 4]);
                af[mt][3] = f2tf32(As[(mm + 8) * APAD + kk + tg + 4]);
            }
#pragma unroll
            for (int nt = 0; nt < 8; ++nt) {
                const int nn = wn * 64 + nt * 8 + gid;
                bf[nt][0] = f2tf32(Bs[(kk + tg) * BPAD + nn]);
                bf[nt][1] = f2tf32(Bs[(kk + tg + 4) * BPAD + nn]);
            }
#pragma unroll
            for (int mt = 0; mt < 4; ++mt)
#pragma unroll
                for (int nt = 0; nt < 8; ++nt) mma_tf32(c[mt][nt], af[mt], bf[nt]);
        }
    }

    // epilogue
#pragma unroll
    for (int mt = 0; mt < 4; ++mt) {
        const int r0 = m0b + wm * 64 + mt * 16 + gid;
#pragma unroll
        for (int nt = 0; nt < 8; ++nt) {
            const int cc = n0b + wn * 64 + nt * 8 + tg * 2;
            *(float2*)&C[(size_t)r0 * N + cc]       = make_float2(c[mt][nt][0], c[mt][nt][1]);
            *(float2*)&C[(size_t)(r0 + 8) * N + cc] = make_float2(c[mt][nt][2], c[mt][nt][3]);
        }
    }
}

// ---------------------------------------------------------------------------
// RoPE (bf16 cos/sin tables, matching reference) + RMSNorm, in place.
// blockIdx.y selects q (0) or k (1).
// ---------------------------------------------------------------------------
__global__ __launch_bounds__(256) void rope_rms_kernel(float* __restrict__ xq,
                                                       float* __restrict__ xk) {
    float* x = blockIdx.y ? xk : xq;
    const int gt   = blockIdx.x * blockDim.x + threadIdx.x;
    const int gw   = gt >> 5;
    const int lane = gt & 31;
    if (gw >= CB * CS * CH) return;

    const int sPos = (gw / CH) % CS;
    float* p = x + (size_t)gw * CHD;

    const float x1 = p[lane];
    const float x2 = p[lane + 32];

    const float ex = (float)(2 * lane) * (1.0f / 64.0f);
    const float fr = powf(100000.0f, ex);
    const float g  = (float)sPos * (1.0f / fr);
    const float cc = __bfloat162float(__float2bfloat16(cosf(g)));
    const float sn = __bfloat162float(__float2bfloat16(sinf(g)));

    const float y1 = x1 * cc + x2 * sn;
    const float y2 = -x1 * sn + x2 * cc;

    float ss = y1 * y1 + y2 * y2;
#pragma unroll
    for (int o = 16; o > 0; o >>= 1) ss += __shfl_xor_sync(0xffffffffu, ss, o);

    const float rms = sqrtf(ss * (1.0f / 64.0f) + 1e-9f);
    const float ir  = 1.0f / rms;
    p[lane]      = y1 * ir;
    p[lane + 32] = y2 * ir;
}

// ---------------------------------------------------------------------------
// Causal flash attention with TF32 tensor cores (unchanged from R6 best).
// ---------------------------------------------------------------------------
__global__ __launch_bounds__(256, 2) void flash_attn_tc(
    const float* __restrict__ q, const float* __restrict__ k,
    const float* __restrict__ v, float* __restrict__ o) {
    __shared__ float Ks[2][32][68];
    __shared__ float Vs[2][32][68];

    const int t    = threadIdx.x;
    const int lane = t & 31;
    const int warp = t >> 5;
    const int gid  = lane >> 2;
    const int tg   = lane & 3;

    const int q0 = (gridDim.x - 1 - blockIdx.x) * 128;
    const int bh = blockIdx.y;
    const size_t base = ((size_t)(bh >> 4) * CS * CH + (bh & 15)) * CHD;
    const int rs = CH * CHD;

    const int qrow0 = q0 + warp * 16 + gid;
    const int qrow1 = qrow0 + 8;

    const int frr = t >> 3;
    const int fdc = (t & 7) * 8;

    uint32_t qa[8][4];
#pragma unroll
    for (int ks = 0; ks < 8; ++ks) {
        qa[ks][0] = f2tf32(0.125f * q[base + (size_t)qrow0 * rs + ks * 8 + tg]);
        qa[ks][1] = f2tf32(0.125f * q[base + (size_t)qrow1 * rs + ks * 8 + tg]);
        qa[ks][2] = f2tf32(0.125f * q[base + (size_t)qrow0 * rs + ks * 8 + tg + 4]);
        qa[ks][3] = f2tf32(0.125f * q[base + (size_t)qrow1 * rs + ks * 8 + tg + 4]);
    }

    float oa[8][4];
#pragma unroll
    for (int dt = 0; dt < 8; ++dt)
#pragma unroll
        for (int i = 0; i < 4; ++i) oa[dt][i] = 0.f;

    float m0 = -1e30f, m1 = -1e30f, l0 = 0.f, l1 = 0.f;

    {
        const size_t gi = base + (size_t)frr * rs + fdc;
        *(float4*)&Ks[0][frr][fdc]     = *(const float4*)&k[gi];
        *(float4*)&Ks[0][frr][fdc + 4] = *(const float4*)&k[gi + 4];
        *(float4*)&Vs[0][frr][fdc]     = *(const float4*)&v[gi];
        *(float4*)&Vs[0][frr][fdc + 4] = *(const float4*)&v[gi + 4];
    }
    __syncthreads();

    const int nkt = (q0 >> 5) + 4;
    for (int kt = 0; kt < nkt; ++kt) {
        const int stage = kt & 1;
        const bool has_next = (kt + 1 < nkt);

        float4 kr0, kr1, vr0, vr1;
        if (has_next) {
            const size_t gi = base + (size_t)(((kt + 1) << 5) + frr) * rs + fdc;
            kr0 = *(const float4*)&k[gi];
            kr1 = *(const float4*)&k[gi + 4];
            vr0 = *(const float4*)&v[gi];
            vr1 = *(const float4*)&v[gi + 4];
        }

        const int kv0 = kt << 5;

        float sc[4][4];
#pragma unroll
        for (int nt = 0; nt < 4; ++nt)
#pragma unroll
            for (int i = 0; i < 4; ++i) sc[nt][i] = 0.f;

#pragma unroll
        for (int ks = 0; ks < 8; ++ks) {
#pragma unroll
            for (int nt = 0; nt < 4; ++nt) {
                uint32_t b[2];
                b[0] = f2tf32(Ks[stage][nt * 8 + gid][ks * 8 + tg]);
                b[1] = f2tf32(Ks[stage][nt * 8 + gid][ks * 8 + tg + 4]);
                mma_tf32(sc[nt], qa[ks], b);
            }
        }

        const bool needmask = (kv0 + 31 > qrow0);
        if (needmask) {
#pragma unroll
            for (int nt = 0; nt < 4; ++nt) {
                const int c0 = kv0 + nt * 8 + 2 * tg;
                const int c1 = c0 + 1;
                if (c0 > qrow0) sc[nt][0] = -1e9f;
                if (c1 > qrow0) sc[nt][1] = -1e9f;
                if (c0 > qrow1) sc[nt][2] = -1e9f;
                if (c1 > qrow1) sc[nt][3] = -1e9f;
            }
        }

        float tm0 = -1e30f, tm1 = -1e30f;
#pragma unroll
        for (int nt = 0; nt < 4; ++nt) {
            tm0 = fmaxf(tm0, fmaxf(sc[nt][0], sc[nt][1]));
            tm1 = fmaxf(tm1, fmaxf(sc[nt][2], sc[nt][3]));
        }
        tm0 = fmaxf(tm0, __shfl_xor_sync(0xffffffffu, tm0, 1));
        tm0 = fmaxf(tm0, __shfl_xor_sync(0xffffffffu, tm0, 2));
        tm1 = fmaxf(tm1, __shfl_xor_sync(0xffffffffu, tm1, 1));
        tm1 = fmaxf(tm1, __shfl_xor_sync(0xffffffffu, tm1, 2));

        const float m0n = fmaxf(m0, tm0);
        const float m1n = fmaxf(m1, tm1);
        const float a0  = __expf(m0 - m0n);
        const float a1  = __expf(m1 - m1n);

        uint32_t pt[4][4];
        float s0 = 0.f, s1 = 0.f;
#pragma unroll
        for (int nt = 0; nt < 4; ++nt) {
            const float p00 = __expf(sc[nt][0] - m0n);
            const float p01 = __expf(sc[nt][1] - m0n);
            const float p10 = __expf(sc[nt][2] - m1n);
            const float p11 = __expf(sc[nt][3] - m1n);
            s0 += p00 + p01;
            s1 += p10 + p11;
            pt[nt][0] = f2tf32(p00);
            pt[nt][1] = f2tf32(p01);
            pt[nt][2] = f2tf32(p10);
            pt[nt][3] = f2tf32(p11);
        }
        s0 += __shfl_xor_sync(0xffffffffu, s0, 1);
        s0 += __shfl_xor_sync(0xffffffffu, s0, 2);
        s1 += __shfl_xor_sync(0xffffffffu, s1, 1);
        s1 += __shfl_xor_sync(0xffffffffu, s1, 2);

        l0 = l0 * a0 + s0;
        l1 = l1 * a1 + s1;
        m0 = m0n;
        m1 = m1n;

#pragma unroll
        for (int dt = 0; dt < 8; ++dt) {
            oa[dt][0] *= a0;
            oa[dt][1] *= a0;
            oa[dt][2] *= a1;
            oa[dt][3] *= a1;
        }

        const int src0 = (lane & ~3) | (tg >> 1);
        const int src2 = src0 + 2;
        const bool odd = (tg & 1);
#pragma unroll
        for (int ks2 = 0; ks2 < 4; ++ks2) {
            uint32_t a00 = __shfl_sync(0xffffffffu, pt[ks2][0], src0);
            uint32_t a01 = __shfl_sync(0xffffffffu, pt[ks2][1], src0);
            uint32_t a10 = __shfl_sync(0xffffffffu, pt[ks2][2], src0);
            uint32_t a11 = __shfl_sync(0xffffffffu, pt[ks2][3], src0);
            uint32_t b00 = __shfl_sync(0xffffffffu, pt[ks2][0], src2);
            uint32_t b01 = __shfl_sync(0xffffffffu, pt[ks2][1], src2);
            uint32_t b10 = __shfl_sync(0xffffffffu, pt[ks2][2], src2);
            uint32_t b11 = __shfl_sync(0xffffffffu, pt[ks2][3], src2);
            uint32_t pa[4];
            pa[0] = odd ? a01 : a00;
            pa[1] = odd ? a11 : a10;
            pa[2] = odd ? b01 : b00;
            pa[3] = odd ? b11 : b10;
#pragma unroll
            for (int dt = 0; dt < 8; ++dt) {
                uint32_t b[2];
                b[0] = f2tf32(Vs[stage][ks2 * 8 + tg][dt * 8 + gid]);
                b[1] = f2tf32(Vs[stage][ks2 * 8 + tg + 4][dt * 8 + gid]);
                mma_tf32(oa[dt], pa, b);
            }
        }

        if (has_next) {
            const int ns = stage ^ 1;
            *(float4*)&Ks[ns][frr][fdc]     = kr0;
            *(float4*)&Ks[ns][frr][fdc + 4] = kr1;
            *(float4*)&Vs[ns][frr][fdc]     = vr0;
            *(float4*)&Vs[ns][frr][fdc + 4] = vr1;
        }
        __syncthreads();
    }

    const float il0 = 1.0f / l0;
    const float il1 = 1.0f / l1;
#pragma unroll
    for (int dt = 0; dt < 8; ++dt) {
        const int cc = dt * 8 + 2 * tg;
        *(float2*)&o[base + (size_t)qrow0 * rs + cc] =
            make_float2(oa[dt][0] * il0, oa[dt][1] * il0);
        *(float2*)&o[base + (size_t)qrow1 * rs + cc] =
            make_float2(oa[dt][2] * il1, oa[dt][3] * il1);
    }
}

// ---------------------------------------------------------------------------
// Launch
// ---------------------------------------------------------------------------
extern "C" void kernel_launch(void* const* d_in, const int* in_sizes, int n_in,
                              void* d_out, int out_size) {
    (void)in_sizes; (void)n_in; (void)out_size;
    const float* Q  = (const float*)d_in[0];
    const float* K  = (const float*)d_in[1];
    const float* V  = (const float*)d_in[2];
    const float* Wq = (const float*)d_in[4];
    const float* Wk = (const float*)d_in[5];
    const float* Wv = (const float*)d_in[6];
    const float* Wo = (const float*)d_in[7];
    float* out = (float*)d_out;

    float *gq, *gk, *gv, *gvals;
    cudaGetSymbolAddress((void**)&gq, g_q);
    cudaGetSymbolAddress((void**)&gk, g_k);
    cudaGetSymbolAddress((void**)&gv, g_v);
    cudaGetSymbolAddress((void**)&gvals, g_vals);

    cudaFuncSetAttribute(sgemm_tf32_v5,
                         cudaFuncAttributeMaxDynamicSharedMemorySize,
                         GEMM_SMEM5);

    const int M = MT;  // 4096

    // Batched QKV projections
    dim3 ggrid3(CD / BN, M / BM, 3);  // (8, 32, 3)
    sgemm_tf32_v5<<<ggrid3, 128, GEMM_SMEM5>>>(Q, K, V, Wq, Wk, Wv, gq, gk, gv,
                                               M, CD, CD);

    const int nwarps = CB * CS * CH;  // 65536
    dim3 rgrid(nwarps / 8, 2);
    rope_rms_kernel<<<rgrid, 256>>>(gq, gk);

    dim3 agrid(CS / 128, CB * CH);    // (16, 32)
    flash_attn_tc<<<agrid, 256>>>(gq, gk, gv, gvals);

    // Output projection
    dim3 ggrid1(CD / BN, M / BM, 1);
    sgemm_tf32_v5<<<ggrid1, 128, GEMM_SMEM5>>>(gvals, nullptr, nullptr, Wo,
                                               nullptr, nullptr, out, nullptr,
                                               nullptr, M, CD, CD);
}